// round 13
// baseline (speedup 1.0000x reference)
#include <cuda_runtime.h>
#include <cuda_bf16.h>

#define B       2
#define NV      16384
#define MOBS    12000
#define NF      16384
#define NCHUNK  4
#define FPC     (NF / NCHUNK)   // 4096 faces per chunk
#define TILE    2048            // faces per smem tile (32KB of float4)
#define T2      256             // threads for nn kernel

// ---- device scratch (no allocations allowed) ----
__device__ float4 g_fc[B * NF];            // (cx, cy, cz, |c|^2 fma-chain)
__device__ float4 g_fn[B * NF];            // next centroid (xyz)
__device__ float4 g_nm[B * NF];            // next normal (xyz, normalized)
__device__ float  g_best[NCHUNK][B * NV];  // per-chunk min score
__device__ int    g_bidx[NCHUNK][B * NV];  // per-chunk argmin face idx
__device__ int    g_gidx[B * NV];          // merged argmin face idx (final)
__device__ int    g_is64;                  // faces dtype: 1 = int64, 0 = int32

// norm^2 with fma contraction, ascending: fma(z,z, fma(y,y, rn(x*x)))
__device__ __forceinline__ float norm2_fma(float x, float y, float z) {
    return __fmaf_rn(z, z, __fmaf_rn(y, y, __fmul_rn(x, x)));
}

// ---------------------------------------------------------------------------
// Kernel 0: probe faces dtype (int64 LE w/ values < 2^31 -> odd words all 0)
// ---------------------------------------------------------------------------
__global__ void decide_kernel(const int* __restrict__ f) {
    int orv = 0;
    for (int j = 0; j < 64; ++j) orv |= f[2 * j + 1];
    g_is64 = (orv == 0) ? 1 : 0;
}

// ---------------------------------------------------------------------------
// Kernel 1: per (batch,face) preprocessing.
// Norm terms FMA-CONTRACTED (matches XLA GPU fusion w/ contract flags —
// confirmed by R4 vs R12 isolated experiment). Mean = ((v0+v1)+v2)/3 true div.
// ---------------------------------------------------------------------------
__global__ void prep_kernel(const float* __restrict__ obs_c,
                            const float* __restrict__ obs_n,
                            const int* __restrict__ faces32) {
    int t = blockIdx.x * blockDim.x + threadIdx.x;
    if (t >= B * NF) return;
    int b = t / NF;

    int i0, i1, i2;
    if (g_is64) {
        i0 = faces32[t * 6 + 0];
        i1 = faces32[t * 6 + 2];
        i2 = faces32[t * 6 + 4];
    } else {
        i0 = faces32[t * 3 + 0];
        i1 = faces32[t * 3 + 1];
        i2 = faces32[t * 3 + 2];
    }
    i0 = min(max(i0, 0), MOBS - 1);
    i1 = min(max(i1, 0), MOBS - 1);
    i2 = min(max(i2, 0), MOBS - 1);

    const float* oc = obs_c + (long long)b * MOBS * 3;
    const float* on = obs_n + (long long)b * MOBS * 3;

    // current centroid: mean = ((v0 + v1) + v2) / 3
    float cx = __fdiv_rn(__fadd_rn(__fadd_rn(oc[i0*3+0], oc[i1*3+0]), oc[i2*3+0]), 3.0f);
    float cy = __fdiv_rn(__fadd_rn(__fadd_rn(oc[i0*3+1], oc[i1*3+1]), oc[i2*3+1]), 3.0f);
    float cz = __fdiv_rn(__fadd_rn(__fadd_rn(oc[i0*3+2], oc[i1*3+2]), oc[i2*3+2]), 3.0f);
    // |c|^2: fma-contracted chain (the critical rounding form)
    g_fc[t] = make_float4(cx, cy, cz, norm2_fma(cx, cy, cz));

    // next positions
    float ax = on[i0*3+0], ay = on[i0*3+1], az = on[i0*3+2];
    float bx = on[i1*3+0], by = on[i1*3+1], bz = on[i1*3+2];
    float dx = on[i2*3+0], dy = on[i2*3+1], dz = on[i2*3+2];

    g_fn[t] = make_float4(
        __fdiv_rn(__fadd_rn(__fadd_rn(ax, bx), dx), 3.0f),
        __fdiv_rn(__fadd_rn(__fadd_rn(ay, by), dy), 3.0f),
        __fdiv_rn(__fadd_rn(__fadd_rn(az, bz), dz), 3.0f), 0.0f);

    // face normal: cross(v1-v0, v2-v0), fma-contracted (a*b - c*d -> fma)
    float e1x = __fsub_rn(bx, ax), e1y = __fsub_rn(by, ay), e1z = __fsub_rn(bz, az);
    float e2x = __fsub_rn(dx, ax), e2y = __fsub_rn(dy, ay), e2z = __fsub_rn(dz, az);
    float nx = __fmaf_rn(e1y, e2z, -__fmul_rn(e1z, e2y));
    float ny = __fmaf_rn(e1z, e2x, -__fmul_rn(e1x, e2z));
    float nz = __fmaf_rn(e1x, e2y, -__fmul_rn(e1y, e2x));
    float nrm = __fadd_rn(__fsqrt_rn(norm2_fma(nx, ny, nz)), 1e-12f);
    g_nm[t] = make_float4(__fdiv_rn(nx, nrm), __fdiv_rn(ny, nrm),
                          __fdiv_rn(nz, nrm), 0.0f);
}

// ---------------------------------------------------------------------------
// Kernel 2: brute-force 1-NN argmin — XLA GPU lowering reconstruction:
//   cn  = fma-contracted |c|^2 (per vertex)
//   dot = fma(cz,fz, fma(cy,fy, rn(cx*fx)))   (cuBLAS ascending-k chain)
//   s   = rn( fma(-2, dot, cn) + fw )         (fusion: contracted sub + add)
// ---------------------------------------------------------------------------
__global__ __launch_bounds__(T2) void nn_kernel(const float* __restrict__ cloth_c) {
    __shared__ float4 sh[TILE];

    int b     = blockIdx.y;
    int chunk = blockIdx.z;
    int n     = blockIdx.x * T2 + threadIdx.x;

    const float* cp = cloth_c + ((long long)b * NV + n) * 3;
    float cx = cp[0], cy = cp[1], cz = cp[2];
    float cn = norm2_fma(cx, cy, cz);

    float best = 3.4e38f;
    int   bidx = 0;
    int   fbase = chunk * FPC;
    const float4* fc = g_fc + b * NF + fbase;

    for (int t0 = 0; t0 < FPC; t0 += TILE) {
        __syncthreads();
        for (int i = threadIdx.x; i < TILE; i += T2) sh[i] = fc[t0 + i];
        __syncthreads();

        #pragma unroll 8
        for (int j = 0; j < TILE; ++j) {
            float4 f = sh[j];  // broadcast load
            float dot = __fmaf_rn(cz, f.z, __fmaf_rn(cy, f.y, __fmul_rn(cx, f.x)));
            float s   = __fadd_rn(__fmaf_rn(-2.0f, dot, cn), f.w);
            bool p = s < best;             // strict < keeps first occurrence
            best = p ? s : best;
            bidx = p ? (fbase + t0 + j) : bidx;
        }
    }
    g_best[chunk][b * NV + n] = best;
    g_bidx[chunk][b * NV + n] = bidx;
}

// ---------------------------------------------------------------------------
// Kernel 2b: merge chunk partials (earlier chunk wins ties -> first index)
// ---------------------------------------------------------------------------
__global__ void combine_kernel() {
    int t = blockIdx.x * blockDim.x + threadIdx.x;
    if (t >= B * NV) return;

    float gb = g_best[0][t];
    int   gi = g_bidx[0][t];
    #pragma unroll
    for (int c = 1; c < NCHUNK; ++c) {
        float v = g_best[c][t];
        if (v < gb) { gb = v; gi = g_bidx[c][t]; }
    }
    g_gidx[t] = gi;
}

// ---------------------------------------------------------------------------
// Kernel 3: plane distance, interpenetration, weight (fma-contracted)
// ---------------------------------------------------------------------------
__global__ void epi_kernel(const float* __restrict__ cloth_n,
                           const int* __restrict__ iterp,
                           float* __restrict__ out) {
    int n = blockIdx.x * blockDim.x + threadIdx.x;
    if (n >= NV) return;

    int iter = iterp ? iterp[0] : 60000;  // low word valid for LE int64 too
    int it = iter - 50000; if (it < 0) it = 0;
    double prog = (double)it / 100000.0;
    if (prog > 1.0) prog = 1.0;
    float weight = (float)(1e-3 + (5e3 - 1e-3) * prog);

    float acc = 0.0f;
    #pragma unroll
    for (int b = 0; b < B; ++b) {
        int bi = g_gidx[b * NV + n];
        float4 p  = g_fn[b * NF + bi];
        float4 nm = g_nm[b * NF + bi];
        const float* q = cloth_n + ((long long)b * NV + n) * 3;
        float dx = __fsub_rn(q[0], p.x);
        float dy = __fsub_rn(q[1], p.y);
        float dz = __fsub_rn(q[2], p.z);
        float dist = __fmaf_rn(dz, nm.z, __fmaf_rn(dy, nm.y, __fmul_rn(dx, nm.x)));
        float t = __fsub_rn(1e-3f, dist);
        t = t > 0.0f ? t : 0.0f;
        float t3 = __fmul_rn(__fmul_rn(t, t), t);
        acc = __fadd_rn(acc, t3);
    }
    out[1 + n] = __fmul_rn(__fmul_rn(acc, 0.5f), weight);  // (v0+v1)/2 * weight
}

// ---------------------------------------------------------------------------
// Kernel 4: deterministic reduction  out[0] = sum(out[1..NV])
// ---------------------------------------------------------------------------
__global__ void red_kernel(float* __restrict__ out) {
    __shared__ float sh[256];
    float s = 0.0f;
    for (int i = threadIdx.x; i < NV; i += 256) s += out[1 + i];
    sh[threadIdx.x] = s;
    __syncthreads();
    for (int k = 128; k > 0; k >>= 1) {
        if (threadIdx.x < k) sh[threadIdx.x] += sh[threadIdx.x + k];
        __syncthreads();
    }
    if (threadIdx.x == 0) out[0] = sh[0];
}

// ---------------------------------------------------------------------------
// Resolve inputs BY SIZE (tolerant to elements-vs-bytes conventions)
// ---------------------------------------------------------------------------
extern "C" void kernel_launch(void* const* d_in, const int* in_sizes, int n_in,
                              void* d_out, int out_size) {
    const float* cloth_curr = nullptr;
    const float* cloth_next = nullptr;
    const float* obs_curr   = nullptr;
    const float* obs_next   = nullptr;
    const int*   faces32    = nullptr;
    const int*   iterp      = nullptr;

    int n_big = 0, n_obs = 0;
    for (int i = 0; i < n_in; ++i) {
        int s = in_sizes[i];
        if (s == 98304 || s == 393216) {
            if (n_big == 0)      cloth_curr = (const float*)d_in[i];
            else if (n_big == 1) cloth_next = (const float*)d_in[i];
            else                 faces32    = (const int*)d_in[i];
            ++n_big;
        } else if (s == 786432) {
            faces32 = (const int*)d_in[i];
        } else if (s == 72000 || s == 288000) {
            if (n_obs == 0) obs_curr = (const float*)d_in[i];
            else            obs_next = (const float*)d_in[i];
            ++n_obs;
        } else if (s == 1 || s == 4 || s == 8) {
            iterp = (const int*)d_in[i];
        }
    }

    float* out = (float*)d_out;

    decide_kernel<<<1, 1>>>(faces32);

    prep_kernel<<<(B * NF + 255) / 256, 256>>>(obs_curr, obs_next, faces32);

    dim3 grid(NV / T2, B, NCHUNK);
    nn_kernel<<<grid, T2>>>(cloth_curr);

    combine_kernel<<<(B * NV + 255) / 256, 256>>>();

    epi_kernel<<<(NV + 255) / 256, 256>>>(cloth_next, iterp, out);

    red_kernel<<<1, 256>>>(out);
}

// round 14
// speedup vs baseline: 1.1427x; 1.1427x over previous
#include <cuda_runtime.h>
#include <cuda_bf16.h>

#define B       2
#define NV      16384
#define MOBS    12000
#define NF      16384
#define NCHUNK  8
#define FPC     (NF / NCHUNK)   // 2048 faces per chunk == one smem tile
#define T2      256             // threads for nn kernel (each handles 2 verts)
#define VPC     (T2 * 2)        // vertices per CTA = 512

// ---- device scratch (no allocations allowed) ----
__device__ float4 g_fc[B * NF];            // (cx, cy, cz, |c|^2 fma-chain)
__device__ float4 g_fn[B * NF];            // next centroid (xyz)
__device__ float4 g_nm[B * NF];            // next normal (xyz, normalized)
__device__ float  g_best[NCHUNK][B * NV];  // per-chunk min score
__device__ int    g_bidx[NCHUNK][B * NV];  // per-chunk argmin face idx

// norm^2 with fma contraction, ascending: fma(z,z, fma(y,y, rn(x*x)))
__device__ __forceinline__ float norm2_fma(float x, float y, float z) {
    return __fmaf_rn(z, z, __fmaf_rn(y, y, __fmul_rn(x, x)));
}

// ---------------------------------------------------------------------------
// Kernel 1: per (batch,face) preprocessing. Faces-dtype probe fused in
// (int64 LE with values < 2^31 -> odd 32-bit words all zero).
// Norm terms FMA-CONTRACTED (critical: confirmed by R4/R12 experiments).
// ---------------------------------------------------------------------------
__global__ void prep_kernel(const float* __restrict__ obs_c,
                            const float* __restrict__ obs_n,
                            const int* __restrict__ faces32) {
    __shared__ int s_is64;
    if (threadIdx.x == 0) {
        int orv = 0;
        #pragma unroll
        for (int j = 0; j < 64; ++j) orv |= faces32[2 * j + 1];
        s_is64 = (orv == 0) ? 1 : 0;
    }
    __syncthreads();

    int t = blockIdx.x * blockDim.x + threadIdx.x;
    if (t >= B * NF) return;
    int b = t / NF;

    int i0, i1, i2;
    if (s_is64) {
        i0 = faces32[t * 6 + 0];
        i1 = faces32[t * 6 + 2];
        i2 = faces32[t * 6 + 4];
    } else {
        i0 = faces32[t * 3 + 0];
        i1 = faces32[t * 3 + 1];
        i2 = faces32[t * 3 + 2];
    }
    i0 = min(max(i0, 0), MOBS - 1);
    i1 = min(max(i1, 0), MOBS - 1);
    i2 = min(max(i2, 0), MOBS - 1);

    const float* oc = obs_c + (long long)b * MOBS * 3;
    const float* on = obs_n + (long long)b * MOBS * 3;

    // current centroid: mean = ((v0 + v1) + v2) / 3
    float cx = __fdiv_rn(__fadd_rn(__fadd_rn(oc[i0*3+0], oc[i1*3+0]), oc[i2*3+0]), 3.0f);
    float cy = __fdiv_rn(__fadd_rn(__fadd_rn(oc[i0*3+1], oc[i1*3+1]), oc[i2*3+1]), 3.0f);
    float cz = __fdiv_rn(__fadd_rn(__fadd_rn(oc[i0*3+2], oc[i1*3+2]), oc[i2*3+2]), 3.0f);
    g_fc[t] = make_float4(cx, cy, cz, norm2_fma(cx, cy, cz));

    // next positions
    float ax = on[i0*3+0], ay = on[i0*3+1], az = on[i0*3+2];
    float bx = on[i1*3+0], by = on[i1*3+1], bz = on[i1*3+2];
    float dx = on[i2*3+0], dy = on[i2*3+1], dz = on[i2*3+2];

    g_fn[t] = make_float4(
        __fdiv_rn(__fadd_rn(__fadd_rn(ax, bx), dx), 3.0f),
        __fdiv_rn(__fadd_rn(__fadd_rn(ay, by), dy), 3.0f),
        __fdiv_rn(__fadd_rn(__fadd_rn(az, bz), dz), 3.0f), 0.0f);

    // face normal: cross(v1-v0, v2-v0), fma-contracted
    float e1x = __fsub_rn(bx, ax), e1y = __fsub_rn(by, ay), e1z = __fsub_rn(bz, az);
    float e2x = __fsub_rn(dx, ax), e2y = __fsub_rn(dy, ay), e2z = __fsub_rn(dz, az);
    float nx = __fmaf_rn(e1y, e2z, -__fmul_rn(e1z, e2y));
    float ny = __fmaf_rn(e1z, e2x, -__fmul_rn(e1x, e2z));
    float nz = __fmaf_rn(e1x, e2y, -__fmul_rn(e1y, e2x));
    float nrm = __fadd_rn(__fsqrt_rn(norm2_fma(nx, ny, nz)), 1e-12f);
    g_nm[t] = make_float4(__fdiv_rn(nx, nrm), __fdiv_rn(ny, nrm),
                          __fdiv_rn(nz, nrm), 0.0f);
}

// ---------------------------------------------------------------------------
// Kernel 2: brute-force 1-NN argmin. Score is BIT-IDENTICAL to R13 (passing):
//   dot = fma(cz,fz, fma(cy,fy, rn(cx*fx)))
//   s   = rn( fma(-2, dot, cn) + fw )
// 2 vertices per thread; one 2048-face smem tile per CTA (no outer loop).
// ---------------------------------------------------------------------------
__global__ __launch_bounds__(T2) void nn_kernel(const float* __restrict__ cloth_c) {
    __shared__ float4 sh[FPC];

    int b     = blockIdx.y;
    int chunk = blockIdx.z;
    int n0    = blockIdx.x * VPC + threadIdx.x;       // vertex A
    int n1    = n0 + T2;                              // vertex B

    const float* cp0 = cloth_c + ((long long)b * NV + n0) * 3;
    const float* cp1 = cloth_c + ((long long)b * NV + n1) * 3;
    float ax = cp0[0], ay = cp0[1], az = cp0[2];
    float bx = cp1[0], by = cp1[1], bz = cp1[2];
    float an = norm2_fma(ax, ay, az);
    float bn = norm2_fma(bx, by, bz);

    int fbase = chunk * FPC;
    const float4* fc = g_fc + b * NF + fbase;

    // load this chunk's faces into smem (coalesced float4)
    for (int i = threadIdx.x; i < FPC; i += T2) sh[i] = fc[i];
    __syncthreads();

    float bestA = 3.4e38f, bestB = 3.4e38f;
    int   idxA  = 0,       idxB  = 0;

    #pragma unroll 8
    for (int j = 0; j < FPC; ++j) {
        float4 f = sh[j];  // broadcast load, shared by both vertices
        float dA = __fmaf_rn(az, f.z, __fmaf_rn(ay, f.y, __fmul_rn(ax, f.x)));
        float sA = __fadd_rn(__fmaf_rn(-2.0f, dA, an), f.w);
        float dB = __fmaf_rn(bz, f.z, __fmaf_rn(by, f.y, __fmul_rn(bx, f.x)));
        float sB = __fadd_rn(__fmaf_rn(-2.0f, dB, bn), f.w);
        bool pA = sA < bestA;                  // strict < -> first occurrence
        bool pB = sB < bestB;
        bestA = pA ? sA : bestA;
        idxA  = pA ? (fbase + j) : idxA;
        bestB = pB ? sB : bestB;
        idxB  = pB ? (fbase + j) : idxB;
    }
    g_best[chunk][b * NV + n0] = bestA;
    g_bidx[chunk][b * NV + n0] = idxA;
    g_best[chunk][b * NV + n1] = bestB;
    g_bidx[chunk][b * NV + n1] = idxB;
}

// ---------------------------------------------------------------------------
// Kernel 3: merge chunk partials (ascending -> first-index ties), plane
// distance, interpenetration, weight. (combine fused in)
// ---------------------------------------------------------------------------
__global__ void epi_kernel(const float* __restrict__ cloth_n,
                           const int* __restrict__ iterp,
                           float* __restrict__ out) {
    int n = blockIdx.x * blockDim.x + threadIdx.x;
    if (n >= NV) return;

    int iter = iterp ? iterp[0] : 60000;  // low word valid for LE int64 too
    int it = iter - 50000; if (it < 0) it = 0;
    double prog = (double)it / 100000.0;
    if (prog > 1.0) prog = 1.0;
    float weight = (float)(1e-3 + (5e3 - 1e-3) * prog);

    float acc = 0.0f;
    #pragma unroll
    for (int b = 0; b < B; ++b) {
        int t = b * NV + n;
        float gb = g_best[0][t];
        int   bi = g_bidx[0][t];
        #pragma unroll
        for (int c = 1; c < NCHUNK; ++c) {
            float v = g_best[c][t];
            if (v < gb) { gb = v; bi = g_bidx[c][t]; }  // earlier chunk wins ties
        }
        float4 p  = g_fn[b * NF + bi];
        float4 nm = g_nm[b * NF + bi];
        const float* q = cloth_n + ((long long)b * NV + n) * 3;
        float dx = __fsub_rn(q[0], p.x);
        float dy = __fsub_rn(q[1], p.y);
        float dz = __fsub_rn(q[2], p.z);
        float dist = __fmaf_rn(dz, nm.z, __fmaf_rn(dy, nm.y, __fmul_rn(dx, nm.x)));
        float t2 = __fsub_rn(1e-3f, dist);
        t2 = t2 > 0.0f ? t2 : 0.0f;
        float t3 = __fmul_rn(__fmul_rn(t2, t2), t2);
        acc = __fadd_rn(acc, t3);
    }
    out[1 + n] = __fmul_rn(__fmul_rn(acc, 0.5f), weight);  // (v0+v1)/2 * weight
}

// ---------------------------------------------------------------------------
// Kernel 4: deterministic reduction  out[0] = sum(out[1..NV])
// ---------------------------------------------------------------------------
__global__ void red_kernel(float* __restrict__ out) {
    __shared__ float sh[256];
    float s = 0.0f;
    for (int i = threadIdx.x; i < NV; i += 256) s += out[1 + i];
    sh[threadIdx.x] = s;
    __syncthreads();
    for (int k = 128; k > 0; k >>= 1) {
        if (threadIdx.x < k) sh[threadIdx.x] += sh[threadIdx.x + k];
        __syncthreads();
    }
    if (threadIdx.x == 0) out[0] = sh[0];
}

// ---------------------------------------------------------------------------
// Resolve inputs BY SIZE (tolerant to elements-vs-bytes conventions)
// ---------------------------------------------------------------------------
extern "C" void kernel_launch(void* const* d_in, const int* in_sizes, int n_in,
                              void* d_out, int out_size) {
    const float* cloth_curr = nullptr;
    const float* cloth_next = nullptr;
    const float* obs_curr   = nullptr;
    const float* obs_next   = nullptr;
    const int*   faces32    = nullptr;
    const int*   iterp      = nullptr;

    int n_big = 0, n_obs = 0;
    for (int i = 0; i < n_in; ++i) {
        int s = in_sizes[i];
        if (s == 98304 || s == 393216) {
            if (n_big == 0)      cloth_curr = (const float*)d_in[i];
            else if (n_big == 1) cloth_next = (const float*)d_in[i];
            else                 faces32    = (const int*)d_in[i];
            ++n_big;
        } else if (s == 786432) {
            faces32 = (const int*)d_in[i];
        } else if (s == 72000 || s == 288000) {
            if (n_obs == 0) obs_curr = (const float*)d_in[i];
            else            obs_next = (const float*)d_in[i];
            ++n_obs;
        } else if (s == 1 || s == 4 || s == 8) {
            iterp = (const int*)d_in[i];
        }
    }

    float* out = (float*)d_out;

    prep_kernel<<<(B * NF + 255) / 256, 256>>>(obs_curr, obs_next, faces32);

    dim3 grid(NV / VPC, B, NCHUNK);   // (32, 2, 8) = 512 CTAs
    nn_kernel<<<grid, T2>>>(cloth_curr);

    epi_kernel<<<(NV + 255) / 256, 256>>>(cloth_next, iterp, out);

    red_kernel<<<1, 256>>>(out);
}